// round 12
// baseline (speedup 1.0000x reference)
#include <cuda_runtime.h>
typedef unsigned long long ull;

constexpr int Bn = 8, Sn = 2048, Pn = 1024, ITERS = 50;
constexpr int CPB = 32, GRID = Bn * CPB, NT = 512;

constexpr float SQI   = 12.011224081528898f;   // sqrt((1/eps)*log2 e)
constexpr float IL2   = 144.26950408889634f;
constexpr float LOG2S = 11.0f;
constexpr float CL    = 80.f;                  // clamp headroom above R

__device__ __align__(16) float g_fs[Bn * Sn];
__device__ __align__(16) float g_gs[Bn * Pn];
__device__ float g_part[GRID];
__device__ unsigned g_cnt[Bn];
__device__ unsigned g_sns[Bn];
__device__ unsigned g_gcnt;

__device__ __forceinline__ float ex2(float x) { float r; asm("ex2.approx.f32 %0, %1;" : "=f"(r) : "f"(x)); return r; }
__device__ __forceinline__ float lg2(float x) { float r; asm("lg2.approx.f32 %0, %1;" : "=f"(r) : "f"(x)); return r; }
__device__ __forceinline__ ull pk(float lo, float hi) { ull r; asm("mov.b64 %0, {%1, %2};" : "=l"(r) : "f"(lo), "f"(hi)); return r; }
__device__ __forceinline__ void upk(ull p, float& a, float& b) { asm("mov.b64 {%0, %1}, %2;" : "=f"(a), "=f"(b) : "l"(p)); }
__device__ __forceinline__ ull add2(ull a, ull b) { ull r; asm("add.rn.f32x2 %0, %1, %2;" : "=l"(r) : "l"(a), "l"(b)); return r; }
__device__ __forceinline__ ull fma2(ull a, ull b, ull c) { ull r; asm("fma.rn.f32x2 %0, %1, %2, %3;" : "=l"(r) : "l"(a), "l"(b), "l"(c)); return r; }
__device__ __forceinline__ float warp_sum(float a) {
    #pragma unroll
    for (int o = 16; o; o >>= 1) a += __shfl_xor_sync(0xffffffffu, a, o);
    return a;
}

// per-batch barrier: release arrive + acquire spin (all CTAs co-resident)
__device__ __forceinline__ void bat_bar(int b, unsigned& ls) {
    ls ^= 1u;
    __syncthreads();
    if (threadIdx.x == 0) {
        unsigned old;
        asm volatile("atom.acq_rel.gpu.add.u32 %0,[%1],%2;"
                     : "=r"(old) : "l"(&g_cnt[b]), "r"(1u) : "memory");
        if (old == CPB - 1) {
            g_cnt[b] = 0;
            asm volatile("st.release.gpu.u32 [%0],%1;" :: "l"(&g_sns[b]), "r"(ls) : "memory");
        } else {
            unsigned v;
            do { asm volatile("ld.acquire.gpu.u32 %0,[%1];" : "=r"(v) : "l"(&g_sns[b]) : "memory"); }
            while (v != ls);
        }
    }
    __syncthreads();
}

__global__ void __launch_bounds__(NT, 2) sinkhorn_kernel(
    const float* __restrict__ pred, const int* __restrict__ labels,
    const float* __restrict__ pos, float* __restrict__ out)
{
    __shared__ __align__(16) float X1[Sn], X2[Sn], Qx[Sn];
    __shared__ __align__(16) float Y1c[Pn], Y2c[Pn], Qyc[Pn], l2bC[Pn];
    __shared__ float sA[512], sRf[64], sRg[32], sred[16];
    __shared__ int swp[8], sPvA[1];

    int tid = threadIdx.x, w = tid >> 5, lane = tid & 31;
    int wg = w & 7, grp = w >> 3;              // 2 groups of 8 warps
    int b = blockIdx.x >> 5, cb = blockIdx.x & 31;
    int row0 = cb * 64;

    // ---- stage X (prescaled by 2*SQI) ----
    const float2* pr2 = (const float2*)pred + b * Sn;
    for (int i = tid; i < Sn; i += NT) {
        float2 p = pr2[i];
        X1[i] = 2.f * SQI * p.x;  X2[i] = 2.f * SQI * p.y;
    }
    // ---- histogram (overlay in Qx region) ----
    int* hist = (int*)Qx;
    for (int i = tid; i < Pn; i += NT) hist[i] = 0;
    __syncthreads();
    const int* lab = labels + b * Sn;
    for (int s = tid; s < Sn; s += NT) atomicAdd(&hist[lab[s]], 1);
    __syncthreads();
    // ---- compact nonzero-weight positions (first 256 threads own 4 slots each) ----
    int c4[4] = {0, 0, 0, 0}, tsum = 0;
    if (tid < 256) {
        #pragma unroll
        for (int k = 0; k < 4; k++) { c4[k] = hist[tid * 4 + k] > 0; tsum += c4[k]; }
    }
    int pre = tsum;
    #pragma unroll
    for (int o = 1; o < 32; o <<= 1) { int v = __shfl_up_sync(~0u, pre, o); if (lane >= o) pre += v; }
    if (w < 8 && lane == 31) swp[w] = pre;
    __syncthreads();
    if (tid == 0) { int r = 0; for (int i = 0; i < 8; i++) { int v = swp[i]; swp[i] = r; r += v; } sPvA[0] = r; }
    __syncthreads();
    int Pv = sPvA[0];
    const float2* po2 = (const float2*)pos + b * Pn;
    if (tid < 256) {
        int off = swp[w] + pre - tsum;
        #pragma unroll
        for (int k = 0; k < 4; k++) {
            if (c4[k]) {
                int p = tid * 4 + k;
                float2 yy = po2[p];
                Y1c[off] = SQI * yy.x;  Y2c[off] = SQI * yy.y;
                l2bC[off] = lg2((float)hist[p] * (1.f / (float)Sn));
                off++;
            }
        }
    }
    __syncthreads();   // hist done; Qx region free until first restage
    int PvPad = (Pv + 15) & ~15;
    for (int i = tid; i < Pn; i += NT) {
        if (i < Pv) Qyc[i] = -(Y1c[i] * Y1c[i] + Y2c[i] * Y2c[i]);   // G=0 -> Qy=-yn
        else { Qyc[i] = -1e30f; Y1c[i] = 0.f; Y2c[i] = 0.f; l2bC[i] = 0.f; }
    }
    unsigned ls = g_sns[b];
    __syncthreads();

    // per-lane constants: f-half row (1 per lane, group-split), g-half col
    int frow = row0 + grp * 32 + lane;
    float X1s = X1[frow], X2s = X2[frow];
    ull X1P = pk(X1s, X1s), X2P = pk(X2s, X2s);
    int cpc = (Pv + CPB - 1) / CPB;
    int myc0 = cb * cpc;
    int myn = min(cpc, max(0, Pv - myc0));
    int gcol = myc0 + ((lane < myn) ? lane : 0);
    float Y1s = Y1c[gcol], Y2s = Y2c[gcol];
    ull Y1p = pk(Y1s, Y1s), Y2p = pk(Y2s, Y2s);
    int nch = PvPad >> 4;

    for (int it = 0; it < ITERS; ++it) {
        // ================= f half: 64 rows, 1/lane, 8-warp chunk stride per group ==
        if (it == 0) {   // seed R: exact row max (fma-only pass)
            float m0 = -3e38f;
            for (int c = wg; c < nch; c += 8) {
                const ull* y1 = (const ull*)(Y1c + c * 16);
                const ull* y2 = (const ull*)(Y2c + c * 16);
                const ull* qq = (const ull*)(Qyc + c * 16);
                #pragma unroll
                for (int j = 0; j < 8; j++) {
                    ull t0 = fma2(X1P, y1[j], fma2(X2P, y2[j], qq[j]));
                    float a, b2; upk(t0, a, b2);
                    m0 = fmaxf(m0, fmaxf(a, b2));
                }
            }
            sA[w * 32 + lane] = m0;
            __syncthreads();
            if (tid < 64) {
                int g = tid >> 5, r = tid & 31;
                float M = -3e38f;
                #pragma unroll
                for (int i = 0; i < 8; i++) M = fmaxf(M, sA[(g * 8 + i) * 32 + r]);
                sRf[tid] = M;
            }
            __syncthreads();
        }
        {
            float R0 = sRf[grp * 32 + lane];
            ull nR0 = pk(-R0, -R0);
            float a0 = 0.f, a1 = 0.f;
            for (int c = wg; c < nch; c += 8) {
                const ull* y1 = (const ull*)(Y1c + c * 16);
                const ull* y2 = (const ull*)(Y2c + c * 16);
                const ull* qq = (const ull*)(Qyc + c * 16);
                #pragma unroll
                for (int j = 0; j < 8; j++) {
                    ull t0 = add2(fma2(X1P, y1[j], fma2(X2P, y2[j], qq[j])), nR0);
                    float ta, tb; upk(t0, ta, tb);
                    a0 += ex2(fminf(ta, CL));
                    a1 += ex2(fminf(tb, CL));
                }
            }
            sA[w * 32 + lane] = a0 + a1;
        }
        __syncthreads();
        if (tid < 64) {
            int g = tid >> 5, r = tid & 31;
            float A = 0.f;
            #pragma unroll
            for (int i = 0; i < 8; i++) A += sA[(g * 8 + i) * 32 + r];
            A = fmaxf(A, 1e-30f);
            float Lse = sRf[tid] + lg2(A);
            sRf[tid] = Lse;
            g_fs[b * Sn + row0 + tid] = -LOG2S - Lse;    // Qx-form directly
        }
        bat_bar(b, ls);
        {
            const ull* src = (const ull*)(g_fs + b * Sn);
            ull* dst = (ull*)Qx;
            for (int i = tid; i < Sn / 2; i += NT) dst[i] = __ldcg(src + i);
        }
        __syncthreads();

        // ================= g half: 16 warps x 128 elements of Sn =================
        if (it == 0) {
            float m = -3e38f;
            const ull* x1 = (const ull*)X1 + w * 64;
            const ull* x2 = (const ull*)X2 + w * 64;
            const ull* qq = (const ull*)Qx + w * 64;
            for (int c = 0; c < 8; c++) {
                #pragma unroll
                for (int j = 0; j < 8; j++) {
                    ull t = fma2(Y1p, x1[c * 8 + j], fma2(Y2p, x2[c * 8 + j], qq[c * 8 + j]));
                    float a, b2; upk(t, a, b2);
                    m = fmaxf(m, fmaxf(a, b2));
                }
            }
            sA[w * 32 + lane] = m;
            __syncthreads();
            if (tid < 32) {
                float M = -3e38f;
                #pragma unroll
                for (int i = 0; i < 16; i++) M = fmaxf(M, sA[i * 32 + tid]);
                sRg[tid] = M;
            }
            __syncthreads();
        }
        {
            float Rg = sRg[lane];
            ull nR = pk(-Rg, -Rg);
            float a0 = 0.f, a1 = 0.f;
            const ull* x1 = (const ull*)X1 + w * 64;
            const ull* x2 = (const ull*)X2 + w * 64;
            const ull* qq = (const ull*)Qx + w * 64;
            for (int c = 0; c < 8; c++) {
                #pragma unroll
                for (int j = 0; j < 8; j++) {
                    ull t = add2(fma2(Y1p, x1[c * 8 + j], fma2(Y2p, x2[c * 8 + j], qq[c * 8 + j])), nR);
                    float ta, tb; upk(t, ta, tb);
                    a0 += ex2(fminf(ta, CL));
                    a1 += ex2(fminf(tb, CL));
                }
            }
            sA[w * 32 + lane] = a0 + a1;
        }
        __syncthreads();
        if (tid < 32) {
            float A = 0.f;
            #pragma unroll
            for (int i = 0; i < 16; i++) A += sA[i * 32 + tid];
            A = fmaxf(A, 1e-30f);
            float Lse = sRg[tid] + lg2(A);
            sRg[tid] = Lse;
            if (tid < myn) g_gs[b * Pn + myc0 + tid] = l2bC[myc0 + tid] - Lse;  // Qy-form
        }
        bat_bar(b, ls);
        for (int i = tid; i < Pv; i += NT) Qyc[i] = __ldcg(&g_gs[b * Pn + i]);
        __syncthreads();
    }

    // ================= final transport distance =================
    {
        float q0 = Qx[frow];
        float xn = 0.25f * (X1s * X1s + X2s * X2s);
        float acc = 0.f;
        for (int c = wg; c < nch; c += 8) {
            const ull* y1 = (const ull*)(Y1c + c * 16);
            const ull* y2 = (const ull*)(Y2c + c * 16);
            const ull* qq = (const ull*)(Qyc + c * 16);
            #pragma unroll
            for (int j = 0; j < 8; j++) {
                ull ly1 = y1[j], ly2 = y2[j], q = qq[j];
                ull t0 = fma2(X1P, ly1, fma2(X2P, ly2, q));
                float qa, qb, y1a, y1b, y2a, y2b, t0a, t0b;
                upk(q, qa, qb); upk(ly1, y1a, y1b); upk(ly2, y2a, y2b);
                upk(t0, t0a, t0b);
                float yna2 = y1a * y1a + y2a * y2a, ynb2 = y1b * y1b + y2b * y2b;
                acc = fmaf(ex2(fminf(t0a + q0, CL)), qa + yna2 + xn - t0a, acc);
                acc = fmaf(ex2(fminf(t0b + q0, CL)), qb + ynb2 + xn - t0b, acc);
            }
        }
        acc = warp_sum(acc);
        if (lane == 0) sred[w] = acc;
    }
    __syncthreads();
    if (tid == 0) {
        float s = 0.f;
        #pragma unroll
        for (int i = 0; i < 16; i++) s += sred[i];
        g_part[blockIdx.x] = s;
    }

    // ---- grid-wide deterministic reduce ----
    __threadfence();
    __syncthreads();
    if (blockIdx.x == 0) {
        if (tid == 0) {
            atomicAdd(&g_gcnt, 1u);
            while (*((volatile unsigned*)&g_gcnt) < (unsigned)GRID) { }
            __threadfence();
        }
        __syncthreads();
        if (tid < 256) sA[tid] = __ldcg(&g_part[tid]);
        __syncthreads();
        #pragma unroll
        for (int o = 128; o; o >>= 1) {
            if (tid < o) sA[tid] += sA[tid + o];
            __syncthreads();
        }
        if (tid == 0) {
            out[0] = sA[0] * (1.f / (IL2 * (float)Bn));
            g_gcnt = 0;
        }
    } else {
        if (tid == 0) atomicAdd(&g_gcnt, 1u);
    }
}

extern "C" void kernel_launch(void* const* d_in, const int* in_sizes, int n_in,
                              void* d_out, int out_size) {
    const float* pred   = (const float*)d_in[0];
    const int*   labels = (const int*)d_in[1];
    const float* pos    = (const float*)d_in[2];
    float*       out    = (float*)d_out;

    sinkhorn_kernel<<<GRID, NT>>>(pred, labels, pos, out);
}

// round 13
// speedup vs baseline: 1.1593x; 1.1593x over previous
#include <cuda_runtime.h>
typedef unsigned long long ull;

constexpr int Bn = 8, Sn = 2048, Pn = 1024, ITERS = 50;
constexpr int CPB = 32, GRID = Bn * CPB, NT = 256;
constexpr int PH = 16;                         // clamped-phase iterations

constexpr float SQI   = 12.011224081528898f;   // sqrt((1/eps)*log2 e)
constexpr float IL2   = 144.26950408889634f;
constexpr float LOG2S = 11.0f;
constexpr float CL    = 110.f;                 // clamp headroom (sum-overflow safe)

__device__ __align__(16) float g_fs[Bn * Sn];
__device__ __align__(16) float g_gs[Bn * Pn];
__device__ float g_part[GRID];
__device__ unsigned g_cnt[Bn];
__device__ unsigned g_sns[Bn];
__device__ unsigned g_gcnt;

__device__ __forceinline__ float ex2(float x) { float r; asm("ex2.approx.f32 %0, %1;" : "=f"(r) : "f"(x)); return r; }
__device__ __forceinline__ float lg2(float x) { float r; asm("lg2.approx.f32 %0, %1;" : "=f"(r) : "f"(x)); return r; }
__device__ __forceinline__ ull pk(float lo, float hi) { ull r; asm("mov.b64 %0, {%1, %2};" : "=l"(r) : "f"(lo), "f"(hi)); return r; }
__device__ __forceinline__ void upk(ull p, float& a, float& b) { asm("mov.b64 {%0, %1}, %2;" : "=f"(a), "=f"(b) : "l"(p)); }
__device__ __forceinline__ ull add2(ull a, ull b) { ull r; asm("add.rn.f32x2 %0, %1, %2;" : "=l"(r) : "l"(a), "l"(b)); return r; }
__device__ __forceinline__ ull fma2(ull a, ull b, ull c) { ull r; asm("fma.rn.f32x2 %0, %1, %2, %3;" : "=l"(r) : "l"(a), "l"(b), "l"(c)); return r; }
__device__ __forceinline__ float warp_sum(float a) {
    #pragma unroll
    for (int o = 16; o; o >>= 1) a += __shfl_xor_sync(0xffffffffu, a, o);
    return a;
}

// per-batch barrier: release arrive + acquire spin (all CTAs co-resident)
__device__ __forceinline__ void bat_bar(int b, unsigned& ls) {
    ls ^= 1u;
    __syncthreads();
    if (threadIdx.x == 0) {
        unsigned old;
        asm volatile("atom.acq_rel.gpu.add.u32 %0,[%1],%2;"
                     : "=r"(old) : "l"(&g_cnt[b]), "r"(1u) : "memory");
        if (old == CPB - 1) {
            g_cnt[b] = 0;
            asm volatile("st.release.gpu.u32 [%0],%1;" :: "l"(&g_sns[b]), "r"(ls) : "memory");
        } else {
            unsigned v;
            do { asm volatile("ld.acquire.gpu.u32 %0,[%1];" : "=r"(v) : "l"(&g_sns[b]) : "memory"); }
            while (v != ls);
        }
    }
    __syncthreads();
}

__global__ void __launch_bounds__(NT, 2) sinkhorn_kernel(
    const float* __restrict__ pred, const int* __restrict__ labels,
    const float* __restrict__ pos, float* __restrict__ out)
{
    __shared__ __align__(16) float X1[Sn], X2[Sn], Qx[Sn];
    __shared__ __align__(16) float Y1c[Pn], Y2c[Pn], Qyc[Pn], l2bC[Pn];
    __shared__ float sA[512], sRf[64], sRg[32], sred[8];
    __shared__ int swp[8], sPvA[1];

    int tid = threadIdx.x, w = tid >> 5, lane = tid & 31;
    int b = blockIdx.x >> 5, cb = blockIdx.x & 31;
    int row0 = cb * 64;

    // ---- stage X (prescaled by 2*SQI) ----
    const float2* pr2 = (const float2*)pred + b * Sn;
    for (int i = tid; i < Sn; i += NT) {
        float2 p = pr2[i];
        X1[i] = 2.f * SQI * p.x;  X2[i] = 2.f * SQI * p.y;
    }
    // ---- histogram (overlay in Qx region) ----
    int* hist = (int*)Qx;
    for (int i = tid; i < Pn; i += NT) hist[i] = 0;
    __syncthreads();
    const int* lab = labels + b * Sn;
    for (int s = tid; s < Sn; s += NT) atomicAdd(&hist[lab[s]], 1);
    __syncthreads();
    // ---- compact nonzero-weight positions (deterministic prefix scan) ----
    int c4[4], tsum = 0;
    #pragma unroll
    for (int k = 0; k < 4; k++) { c4[k] = hist[tid * 4 + k] > 0; tsum += c4[k]; }
    int pre = tsum;
    #pragma unroll
    for (int o = 1; o < 32; o <<= 1) { int v = __shfl_up_sync(~0u, pre, o); if (lane >= o) pre += v; }
    if (lane == 31) swp[w] = pre;
    __syncthreads();
    if (tid == 0) { int r = 0; for (int i = 0; i < 8; i++) { int v = swp[i]; swp[i] = r; r += v; } sPvA[0] = r; }
    __syncthreads();
    int Pv = sPvA[0];
    int off = swp[w] + pre - tsum;
    const float2* po2 = (const float2*)pos + b * Pn;
    #pragma unroll
    for (int k = 0; k < 4; k++) {
        if (c4[k]) {
            int p = tid * 4 + k;
            float2 yy = po2[p];
            Y1c[off] = SQI * yy.x;  Y2c[off] = SQI * yy.y;
            l2bC[off] = lg2((float)hist[p] * (1.f / (float)Sn));
            off++;
        }
    }
    __syncthreads();   // hist done; Qx region free until first restage
    int PvPad = (Pv + 15) & ~15;
    for (int i = tid; i < Pn; i += NT) {
        if (i < Pv) Qyc[i] = -(Y1c[i] * Y1c[i] + Y2c[i] * Y2c[i]);   // G=0 -> Qy=-yn
        else { Qyc[i] = -1e30f; Y1c[i] = 0.f; Y2c[i] = 0.f; l2bC[i] = 0.f; }
    }
    unsigned ls = g_sns[b];
    __syncthreads();

    // per-lane constants
    int fr0 = row0 + lane, fr1 = fr0 + 32;
    float X1a = X1[fr0], X2a = X2[fr0], X1b_ = X1[fr1], X2b_ = X2[fr1];
    ull X1A = pk(X1a, X1a), X2A = pk(X2a, X2a);
    ull X1B = pk(X1b_, X1b_), X2B = pk(X2b_, X2b_);
    int cpc = (Pv + CPB - 1) / CPB;
    int myc0 = cb * cpc;
    int myn = min(cpc, max(0, Pv - myc0));
    int gcol = myc0 + ((lane < myn) ? lane : 0);
    float Y1s = Y1c[gcol], Y2s = Y2c[gcol];
    ull Y1p = pk(Y1s, Y1s), Y2p = pk(Y2s, Y2s);
    int nch = PvPad >> 4;

    for (int it = 0; it < ITERS; ++it) {
        // ================= f half =================
        if (it == 0) {   // seed R: exact row max (fma-only pass)
            float m0 = -3e38f, m1 = -3e38f;
            for (int c = w; c < nch; c += 8) {
                const ulonglong2* y1 = (const ulonglong2*)(Y1c + c * 16);
                const ulonglong2* y2 = (const ulonglong2*)(Y2c + c * 16);
                const ulonglong2* qq = (const ulonglong2*)(Qyc + c * 16);
                #pragma unroll
                for (int j = 0; j < 4; j++) {
                    ulonglong2 ly1 = y1[j], ly2 = y2[j], q = qq[j];
                    ull t;
                    float a, b2;
                    t = fma2(X1A, ly1.x, fma2(X2A, ly2.x, q.x));
                    upk(t, a, b2); m0 = fmaxf(m0, fmaxf(a, b2));
                    t = fma2(X1A, ly1.y, fma2(X2A, ly2.y, q.y));
                    upk(t, a, b2); m0 = fmaxf(m0, fmaxf(a, b2));
                    t = fma2(X1B, ly1.x, fma2(X2B, ly2.x, q.x));
                    upk(t, a, b2); m1 = fmaxf(m1, fmaxf(a, b2));
                    t = fma2(X1B, ly1.y, fma2(X2B, ly2.y, q.y));
                    upk(t, a, b2); m1 = fmaxf(m1, fmaxf(a, b2));
                }
            }
            sA[w * 64 + lane] = m0;  sA[w * 64 + lane + 32] = m1;
            __syncthreads();
            if (tid < 64) {
                float M = -3e38f;
                #pragma unroll
                for (int i = 0; i < 8; i++) M = fmaxf(M, sA[i * 64 + tid]);
                sRf[tid] = M;
            }
            __syncthreads();
        }
        {
            float R0 = sRf[lane], R1 = sRf[lane + 32];
            ull nR0 = pk(-R0, -R0), nR1 = pk(-R1, -R1);
            float a0 = 0.f, a1 = 0.f, a2 = 0.f, a3 = 0.f;
            if (it < PH) {
                for (int c = w; c < nch; c += 8) {
                    const ulonglong2* y1 = (const ulonglong2*)(Y1c + c * 16);
                    const ulonglong2* y2 = (const ulonglong2*)(Y2c + c * 16);
                    const ulonglong2* qq = (const ulonglong2*)(Qyc + c * 16);
                    #pragma unroll
                    for (int j = 0; j < 4; j++) {
                        ulonglong2 ly1 = y1[j], ly2 = y2[j], q = qq[j];
                        ull t; float ta, tb;
                        t = add2(fma2(X1A, ly1.x, fma2(X2A, ly2.x, q.x)), nR0);
                        upk(t, ta, tb);
                        a0 += ex2(fminf(ta, CL)); a1 += ex2(fminf(tb, CL));
                        t = add2(fma2(X1A, ly1.y, fma2(X2A, ly2.y, q.y)), nR0);
                        upk(t, ta, tb);
                        a0 += ex2(fminf(ta, CL)); a1 += ex2(fminf(tb, CL));
                        t = add2(fma2(X1B, ly1.x, fma2(X2B, ly2.x, q.x)), nR1);
                        upk(t, ta, tb);
                        a2 += ex2(fminf(ta, CL)); a3 += ex2(fminf(tb, CL));
                        t = add2(fma2(X1B, ly1.y, fma2(X2B, ly2.y, q.y)), nR1);
                        upk(t, ta, tb);
                        a2 += ex2(fminf(ta, CL)); a3 += ex2(fminf(tb, CL));
                    }
                }
            } else {
                for (int c = w; c < nch; c += 8) {
                    const ulonglong2* y1 = (const ulonglong2*)(Y1c + c * 16);
                    const ulonglong2* y2 = (const ulonglong2*)(Y2c + c * 16);
                    const ulonglong2* qq = (const ulonglong2*)(Qyc + c * 16);
                    #pragma unroll
                    for (int j = 0; j < 4; j++) {
                        ulonglong2 ly1 = y1[j], ly2 = y2[j], q = qq[j];
                        ull t; float ta, tb;
                        t = add2(fma2(X1A, ly1.x, fma2(X2A, ly2.x, q.x)), nR0);
                        upk(t, ta, tb);
                        a0 += ex2(ta); a1 += ex2(tb);
                        t = add2(fma2(X1A, ly1.y, fma2(X2A, ly2.y, q.y)), nR0);
                        upk(t, ta, tb);
                        a0 += ex2(ta); a1 += ex2(tb);
                        t = add2(fma2(X1B, ly1.x, fma2(X2B, ly2.x, q.x)), nR1);
                        upk(t, ta, tb);
                        a2 += ex2(ta); a3 += ex2(tb);
                        t = add2(fma2(X1B, ly1.y, fma2(X2B, ly2.y, q.y)), nR1);
                        upk(t, ta, tb);
                        a2 += ex2(ta); a3 += ex2(tb);
                    }
                }
            }
            sA[w * 64 + lane] = a0 + a1;  sA[w * 64 + lane + 32] = a2 + a3;
        }
        __syncthreads();
        if (tid < 64) {
            float A = 0.f;
            #pragma unroll
            for (int i = 0; i < 8; i++) A += sA[i * 64 + tid];
            A = fmaxf(A, 1e-30f);
            float Lse = sRf[tid] + lg2(A);
            sRf[tid] = Lse;
            g_fs[b * Sn + row0 + tid] = -LOG2S - Lse;    // Qx-form directly
        }
        bat_bar(b, ls);
        {
            const ull* src = (const ull*)(g_fs + b * Sn);
            ull* dst = (ull*)Qx;
            for (int i = tid; i < Sn / 2; i += NT) dst[i] = __ldcg(src + i);
        }
        __syncthreads();

        // ================= g half =================
        if (it == 0) {
            float m = -3e38f;
            const ulonglong2* x1 = (const ulonglong2*)(X1 + w * 256);
            const ulonglong2* x2 = (const ulonglong2*)(X2 + w * 256);
            const ulonglong2* qq = (const ulonglong2*)(Qx + w * 256);
            for (int c = 0; c < 64; c++) {
                ulonglong2 lx1 = x1[c], lx2 = x2[c], q = qq[c];
                ull t; float a, b2;
                t = fma2(Y1p, lx1.x, fma2(Y2p, lx2.x, q.x));
                upk(t, a, b2); m = fmaxf(m, fmaxf(a, b2));
                t = fma2(Y1p, lx1.y, fma2(Y2p, lx2.y, q.y));
                upk(t, a, b2); m = fmaxf(m, fmaxf(a, b2));
            }
            sA[w * 64 + lane] = m;
            __syncthreads();
            if (tid < 32) {
                float M = -3e38f;
                #pragma unroll
                for (int i = 0; i < 8; i++) M = fmaxf(M, sA[i * 64 + tid]);
                sRg[tid] = M;
            }
            __syncthreads();
        }
        {
            float Rg = sRg[lane];
            ull nR = pk(-Rg, -Rg);
            float a0 = 0.f, a1 = 0.f;
            const ulonglong2* x1 = (const ulonglong2*)(X1 + w * 256);
            const ulonglong2* x2 = (const ulonglong2*)(X2 + w * 256);
            const ulonglong2* qq = (const ulonglong2*)(Qx + w * 256);
            if (it < PH) {
                #pragma unroll 4
                for (int c = 0; c < 64; c++) {
                    ulonglong2 lx1 = x1[c], lx2 = x2[c], q = qq[c];
                    ull t; float ta, tb;
                    t = add2(fma2(Y1p, lx1.x, fma2(Y2p, lx2.x, q.x)), nR);
                    upk(t, ta, tb);
                    a0 += ex2(fminf(ta, CL)); a1 += ex2(fminf(tb, CL));
                    t = add2(fma2(Y1p, lx1.y, fma2(Y2p, lx2.y, q.y)), nR);
                    upk(t, ta, tb);
                    a0 += ex2(fminf(ta, CL)); a1 += ex2(fminf(tb, CL));
                }
            } else {
                #pragma unroll 4
                for (int c = 0; c < 64; c++) {
                    ulonglong2 lx1 = x1[c], lx2 = x2[c], q = qq[c];
                    ull t; float ta, tb;
                    t = add2(fma2(Y1p, lx1.x, fma2(Y2p, lx2.x, q.x)), nR);
                    upk(t, ta, tb);
                    a0 += ex2(ta); a1 += ex2(tb);
                    t = add2(fma2(Y1p, lx1.y, fma2(Y2p, lx2.y, q.y)), nR);
                    upk(t, ta, tb);
                    a0 += ex2(ta); a1 += ex2(tb);
                }
            }
            sA[w * 64 + lane] = a0 + a1;
        }
        __syncthreads();
        if (tid < 32) {
            float A = 0.f;
            #pragma unroll
            for (int i = 0; i < 8; i++) A += sA[i * 64 + tid];
            A = fmaxf(A, 1e-30f);
            float Lse = sRg[tid] + lg2(A);
            sRg[tid] = Lse;
            if (tid < myn) g_gs[b * Pn + myc0 + tid] = l2bC[myc0 + tid] - Lse;  // Qy-form
        }
        bat_bar(b, ls);
        for (int i = tid; i < Pv; i += NT) Qyc[i] = __ldcg(&g_gs[b * Pn + i]);
        __syncthreads();
    }

    // ================= final transport distance =================
    {
        float q0 = Qx[fr0], q1 = Qx[fr1];
        float xna = 0.25f * (X1a * X1a + X2a * X2a);
        float xnb = 0.25f * (X1b_ * X1b_ + X2b_ * X2b_);
        float acc = 0.f;
        for (int c = w; c < nch; c += 8) {
            const ull* y1 = (const ull*)(Y1c + c * 16);
            const ull* y2 = (const ull*)(Y2c + c * 16);
            const ull* qq = (const ull*)(Qyc + c * 16);
            #pragma unroll
            for (int j = 0; j < 8; j++) {
                ull ly1 = y1[j], ly2 = y2[j], q = qq[j];
                ull t0 = fma2(X1A, ly1, fma2(X2A, ly2, q));
                ull t1 = fma2(X1B, ly1, fma2(X2B, ly2, q));
                float qa, qb, y1a, y1b, y2a, y2b, t0a, t0b, t1a, t1b;
                upk(q, qa, qb); upk(ly1, y1a, y1b); upk(ly2, y2a, y2b);
                upk(t0, t0a, t0b); upk(t1, t1a, t1b);
                float yna2 = y1a * y1a + y2a * y2a, ynb2 = y1b * y1b + y2b * y2b;
                acc = fmaf(ex2(fminf(t0a + q0, CL)), qa + yna2 + xna - t0a, acc);
                acc = fmaf(ex2(fminf(t0b + q0, CL)), qb + ynb2 + xna - t0b, acc);
                acc = fmaf(ex2(fminf(t1a + q1, CL)), qa + yna2 + xnb - t1a, acc);
                acc = fmaf(ex2(fminf(t1b + q1, CL)), qb + ynb2 + xnb - t1b, acc);
            }
        }
        acc = warp_sum(acc);
        if (lane == 0) sred[w] = acc;
    }
    __syncthreads();
    if (tid == 0) {
        float s = 0.f;
        #pragma unroll
        for (int i = 0; i < 8; i++) s += sred[i];
        g_part[blockIdx.x] = s;
    }

    // ---- grid-wide deterministic reduce ----
    __threadfence();
    __syncthreads();
    if (blockIdx.x == 0) {
        if (tid == 0) {
            atomicAdd(&g_gcnt, 1u);
            while (*((volatile unsigned*)&g_gcnt) < (unsigned)GRID) { }
            __threadfence();
        }
        __syncthreads();
        sA[tid] = __ldcg(&g_part[tid]);
        __syncthreads();
        #pragma unroll
        for (int o = 128; o; o >>= 1) {
            if (tid < o) sA[tid] += sA[tid + o];
            __syncthreads();
        }
        if (tid == 0) {
            out[0] = sA[0] * (1.f / (IL2 * (float)Bn));
            g_gcnt = 0;
        }
    } else {
        if (tid == 0) atomicAdd(&g_gcnt, 1u);
    }
}

extern "C" void kernel_launch(void* const* d_in, const int* in_sizes, int n_in,
                              void* d_out, int out_size) {
    const float* pred   = (const float*)d_in[0];
    const int*   labels = (const int*)d_in[1];
    const float* pos    = (const float*)d_in[2];
    float*       out    = (float*)d_out;

    sinkhorn_kernel<<<GRID, NT>>>(pred, labels, pos, out);
}

// round 14
// speedup vs baseline: 1.1880x; 1.0248x over previous
#include <cuda_runtime.h>
typedef unsigned long long ull;

constexpr int Bn = 8, Sn = 2048, Pn = 1024, ITERS = 50;
constexpr int CPB = 32, GRID = Bn * CPB, NT = 384;
constexpr int NW = NT / 32;                    // 12 warps
constexpr int PH = 16;                         // clamped-phase iterations

constexpr float SQI   = 12.011224081528898f;   // sqrt((1/eps)*log2 e)
constexpr float IL2   = 144.26950408889634f;
constexpr float LOG2S = 11.0f;
constexpr float CL    = 110.f;                 // clamp headroom (sum-overflow safe)

__device__ __align__(16) float g_fs[Bn * Sn];
__device__ __align__(16) float g_gs[Bn * Pn];
__device__ float g_part[GRID];
__device__ unsigned g_cnt[Bn];
__device__ unsigned g_sns[Bn];
__device__ unsigned g_gcnt;

__device__ __forceinline__ float ex2(float x) { float r; asm("ex2.approx.f32 %0, %1;" : "=f"(r) : "f"(x)); return r; }
__device__ __forceinline__ float lg2(float x) { float r; asm("lg2.approx.f32 %0, %1;" : "=f"(r) : "f"(x)); return r; }
__device__ __forceinline__ ull pk(float lo, float hi) { ull r; asm("mov.b64 %0, {%1, %2};" : "=l"(r) : "f"(lo), "f"(hi)); return r; }
__device__ __forceinline__ void upk(ull p, float& a, float& b) { asm("mov.b64 {%0, %1}, %2;" : "=f"(a), "=f"(b) : "l"(p)); }
__device__ __forceinline__ ull add2(ull a, ull b) { ull r; asm("add.rn.f32x2 %0, %1, %2;" : "=l"(r) : "l"(a), "l"(b)); return r; }
__device__ __forceinline__ ull fma2(ull a, ull b, ull c) { ull r; asm("fma.rn.f32x2 %0, %1, %2, %3;" : "=l"(r) : "l"(a), "l"(b), "l"(c)); return r; }
__device__ __forceinline__ float warp_sum(float a) {
    #pragma unroll
    for (int o = 16; o; o >>= 1) a += __shfl_xor_sync(0xffffffffu, a, o);
    return a;
}

// per-batch barrier: release arrive + acquire spin (all CTAs co-resident)
__device__ __forceinline__ void bat_bar(int b, unsigned& ls) {
    ls ^= 1u;
    __syncthreads();
    if (threadIdx.x == 0) {
        unsigned old;
        asm volatile("atom.acq_rel.gpu.add.u32 %0,[%1],%2;"
                     : "=r"(old) : "l"(&g_cnt[b]), "r"(1u) : "memory");
        if (old == CPB - 1) {
            g_cnt[b] = 0;
            asm volatile("st.release.gpu.u32 [%0],%1;" :: "l"(&g_sns[b]), "r"(ls) : "memory");
        } else {
            unsigned v;
            do { asm volatile("ld.acquire.gpu.u32 %0,[%1];" : "=r"(v) : "l"(&g_sns[b]) : "memory"); }
            while (v != ls);
        }
    }
    __syncthreads();
}

__global__ void __launch_bounds__(NT, 2) sinkhorn_kernel(
    const float* __restrict__ pred, const int* __restrict__ labels,
    const float* __restrict__ pos, float* __restrict__ out)
{
    __shared__ __align__(16) float X1[Sn], X2[Sn], Qx[Sn];
    __shared__ __align__(16) float Y1c[Pn], Y2c[Pn], Qyc[Pn], l2bC[Pn];
    __shared__ float sA[NW * 64], sRf[64], sRg[32], sred[NW];
    __shared__ int swp[8], sPvA[1];

    int tid = threadIdx.x, w = tid >> 5, lane = tid & 31;
    int b = blockIdx.x >> 5, cb = blockIdx.x & 31;
    int row0 = cb * 64;

    // ---- stage X (prescaled by 2*SQI) ----
    const float2* pr2 = (const float2*)pred + b * Sn;
    for (int i = tid; i < Sn; i += NT) {
        float2 p = pr2[i];
        X1[i] = 2.f * SQI * p.x;  X2[i] = 2.f * SQI * p.y;
    }
    // ---- histogram (overlay in Qx region) ----
    int* hist = (int*)Qx;
    for (int i = tid; i < Pn; i += NT) hist[i] = 0;
    __syncthreads();
    const int* lab = labels + b * Sn;
    for (int s = tid; s < Sn; s += NT) atomicAdd(&hist[lab[s]], 1);
    __syncthreads();
    // ---- compact nonzero-weight positions (first 8 warps, 4 slots/thread) ----
    int c4[4] = {0, 0, 0, 0}, tsum = 0;
    if (tid < 256) {
        #pragma unroll
        for (int k = 0; k < 4; k++) { c4[k] = hist[tid * 4 + k] > 0; tsum += c4[k]; }
    }
    int pre = tsum;
    #pragma unroll
    for (int o = 1; o < 32; o <<= 1) { int v = __shfl_up_sync(~0u, pre, o); if (lane >= o) pre += v; }
    if (w < 8 && lane == 31) swp[w] = pre;
    __syncthreads();
    if (tid == 0) { int r = 0; for (int i = 0; i < 8; i++) { int v = swp[i]; swp[i] = r; r += v; } sPvA[0] = r; }
    __syncthreads();
    int Pv = sPvA[0];
    const float2* po2 = (const float2*)pos + b * Pn;
    if (tid < 256) {
        int off = swp[w] + pre - tsum;
        #pragma unroll
        for (int k = 0; k < 4; k++) {
            if (c4[k]) {
                int p = tid * 4 + k;
                float2 yy = po2[p];
                Y1c[off] = SQI * yy.x;  Y2c[off] = SQI * yy.y;
                l2bC[off] = lg2((float)hist[p] * (1.f / (float)Sn));
                off++;
            }
        }
    }
    __syncthreads();   // hist done; Qx region free until first restage
    int PvPad = (Pv + 15) & ~15;
    for (int i = tid; i < Pn; i += NT) {
        if (i < Pv) Qyc[i] = -(Y1c[i] * Y1c[i] + Y2c[i] * Y2c[i]);   // G=0 -> Qy=-yn
        else { Qyc[i] = -1e30f; Y1c[i] = 0.f; Y2c[i] = 0.f; l2bC[i] = 0.f; }
    }
    unsigned ls = g_sns[b];
    __syncthreads();

    // per-lane constants
    int fr0 = row0 + lane, fr1 = fr0 + 32;
    float X1a = X1[fr0], X2a = X2[fr0], X1b_ = X1[fr1], X2b_ = X2[fr1];
    ull X1A = pk(X1a, X1a), X2A = pk(X2a, X2a);
    ull X1B = pk(X1b_, X1b_), X2B = pk(X2b_, X2b_);
    int cpc = (Pv + CPB - 1) / CPB;
    int myc0 = cb * cpc;
    int myn = min(cpc, max(0, Pv - myc0));
    int gcol = myc0 + ((lane < myn) ? lane : 0);
    float Y1s = Y1c[gcol], Y2s = Y2c[gcol];
    ull Y1p = pk(Y1s, Y1s), Y2p = pk(Y2s, Y2s);
    int nch = PvPad >> 4;

    for (int it = 0; it < ITERS; ++it) {
        // ================= f half: 64 rows (2/lane), 12 warps stride chunks ====
        if (it == 0) {   // seed R: exact row max (fma-only pass)
            float m0 = -3e38f, m1 = -3e38f;
            for (int c = w; c < nch; c += NW) {
                const ulonglong2* y1 = (const ulonglong2*)(Y1c + c * 16);
                const ulonglong2* y2 = (const ulonglong2*)(Y2c + c * 16);
                const ulonglong2* qq = (const ulonglong2*)(Qyc + c * 16);
                #pragma unroll
                for (int j = 0; j < 4; j++) {
                    ulonglong2 ly1 = y1[j], ly2 = y2[j], q = qq[j];
                    ull t; float a, b2;
                    t = fma2(X1A, ly1.x, fma2(X2A, ly2.x, q.x));
                    upk(t, a, b2); m0 = fmaxf(m0, fmaxf(a, b2));
                    t = fma2(X1A, ly1.y, fma2(X2A, ly2.y, q.y));
                    upk(t, a, b2); m0 = fmaxf(m0, fmaxf(a, b2));
                    t = fma2(X1B, ly1.x, fma2(X2B, ly2.x, q.x));
                    upk(t, a, b2); m1 = fmaxf(m1, fmaxf(a, b2));
                    t = fma2(X1B, ly1.y, fma2(X2B, ly2.y, q.y));
                    upk(t, a, b2); m1 = fmaxf(m1, fmaxf(a, b2));
                }
            }
            sA[w * 64 + lane] = m0;  sA[w * 64 + lane + 32] = m1;
            __syncthreads();
            if (tid < 64) {
                float M = -3e38f;
                #pragma unroll
                for (int i = 0; i < NW; i++) M = fmaxf(M, sA[i * 64 + tid]);
                sRf[tid] = M;
            }
            __syncthreads();
        }
        {
            float R0 = sRf[lane], R1 = sRf[lane + 32];
            ull nR0 = pk(-R0, -R0), nR1 = pk(-R1, -R1);
            float a0 = 0.f, a1 = 0.f, a2 = 0.f, a3 = 0.f;
            if (it < PH) {
                for (int c = w; c < nch; c += NW) {
                    const ulonglong2* y1 = (const ulonglong2*)(Y1c + c * 16);
                    const ulonglong2* y2 = (const ulonglong2*)(Y2c + c * 16);
                    const ulonglong2* qq = (const ulonglong2*)(Qyc + c * 16);
                    #pragma unroll
                    for (int j = 0; j < 4; j++) {
                        ulonglong2 ly1 = y1[j], ly2 = y2[j], q = qq[j];
                        ull t; float ta, tb;
                        t = add2(fma2(X1A, ly1.x, fma2(X2A, ly2.x, q.x)), nR0);
                        upk(t, ta, tb);
                        a0 += ex2(fminf(ta, CL)); a1 += ex2(fminf(tb, CL));
                        t = add2(fma2(X1A, ly1.y, fma2(X2A, ly2.y, q.y)), nR0);
                        upk(t, ta, tb);
                        a0 += ex2(fminf(ta, CL)); a1 += ex2(fminf(tb, CL));
                        t = add2(fma2(X1B, ly1.x, fma2(X2B, ly2.x, q.x)), nR1);
                        upk(t, ta, tb);
                        a2 += ex2(fminf(ta, CL)); a3 += ex2(fminf(tb, CL));
                        t = add2(fma2(X1B, ly1.y, fma2(X2B, ly2.y, q.y)), nR1);
                        upk(t, ta, tb);
                        a2 += ex2(fminf(ta, CL)); a3 += ex2(fminf(tb, CL));
                    }
                }
            } else {
                for (int c = w; c < nch; c += NW) {
                    const ulonglong2* y1 = (const ulonglong2*)(Y1c + c * 16);
                    const ulonglong2* y2 = (const ulonglong2*)(Y2c + c * 16);
                    const ulonglong2* qq = (const ulonglong2*)(Qyc + c * 16);
                    #pragma unroll
                    for (int j = 0; j < 4; j++) {
                        ulonglong2 ly1 = y1[j], ly2 = y2[j], q = qq[j];
                        ull t; float ta, tb;
                        t = add2(fma2(X1A, ly1.x, fma2(X2A, ly2.x, q.x)), nR0);
                        upk(t, ta, tb);
                        a0 += ex2(ta); a1 += ex2(tb);
                        t = add2(fma2(X1A, ly1.y, fma2(X2A, ly2.y, q.y)), nR0);
                        upk(t, ta, tb);
                        a0 += ex2(ta); a1 += ex2(tb);
                        t = add2(fma2(X1B, ly1.x, fma2(X2B, ly2.x, q.x)), nR1);
                        upk(t, ta, tb);
                        a2 += ex2(ta); a3 += ex2(tb);
                        t = add2(fma2(X1B, ly1.y, fma2(X2B, ly2.y, q.y)), nR1);
                        upk(t, ta, tb);
                        a2 += ex2(ta); a3 += ex2(tb);
                    }
                }
            }
            sA[w * 64 + lane] = a0 + a1;  sA[w * 64 + lane + 32] = a2 + a3;
        }
        __syncthreads();
        if (tid < 64) {
            float A = 0.f;
            #pragma unroll
            for (int i = 0; i < NW; i++) A += sA[i * 64 + tid];
            A = fmaxf(A, 1e-30f);
            float Lse = sRf[tid] + lg2(A);
            sRf[tid] = Lse;
            g_fs[b * Sn + row0 + tid] = -LOG2S - Lse;    // Qx-form directly
        }
        bat_bar(b, ls);
        {
            const ull* src = (const ull*)(g_fs + b * Sn);
            ull* dst = (ull*)Qx;
            for (int i = tid; i < Sn / 2; i += NT) dst[i] = __ldcg(src + i);
        }
        __syncthreads();

        // ================= g half: 128 chunks of 16, 12 warps stride ==========
        if (it == 0) {
            float m = -3e38f;
            for (int c = w; c < 128; c += NW) {
                const ulonglong2* x1 = (const ulonglong2*)(X1 + c * 16);
                const ulonglong2* x2 = (const ulonglong2*)(X2 + c * 16);
                const ulonglong2* qq = (const ulonglong2*)(Qx + c * 16);
                #pragma unroll
                for (int j = 0; j < 4; j++) {
                    ulonglong2 lx1 = x1[j], lx2 = x2[j], q = qq[j];
                    ull t; float a, b2;
                    t = fma2(Y1p, lx1.x, fma2(Y2p, lx2.x, q.x));
                    upk(t, a, b2); m = fmaxf(m, fmaxf(a, b2));
                    t = fma2(Y1p, lx1.y, fma2(Y2p, lx2.y, q.y));
                    upk(t, a, b2); m = fmaxf(m, fmaxf(a, b2));
                }
            }
            sA[w * 64 + lane] = m;
            __syncthreads();
            if (tid < 32) {
                float M = -3e38f;
                #pragma unroll
                for (int i = 0; i < NW; i++) M = fmaxf(M, sA[i * 64 + tid]);
                sRg[tid] = M;
            }
            __syncthreads();
        }
        {
            float Rg = sRg[lane];
            ull nR = pk(-Rg, -Rg);
            float a0 = 0.f, a1 = 0.f;
            if (it < PH) {
                for (int c = w; c < 128; c += NW) {
                    const ulonglong2* x1 = (const ulonglong2*)(X1 + c * 16);
                    const ulonglong2* x2 = (const ulonglong2*)(X2 + c * 16);
                    const ulonglong2* qq = (const ulonglong2*)(Qx + c * 16);
                    #pragma unroll
                    for (int j = 0; j < 4; j++) {
                        ulonglong2 lx1 = x1[j], lx2 = x2[j], q = qq[j];
                        ull t; float ta, tb;
                        t = add2(fma2(Y1p, lx1.x, fma2(Y2p, lx2.x, q.x)), nR);
                        upk(t, ta, tb);
                        a0 += ex2(fminf(ta, CL)); a1 += ex2(fminf(tb, CL));
                        t = add2(fma2(Y1p, lx1.y, fma2(Y2p, lx2.y, q.y)), nR);
                        upk(t, ta, tb);
                        a0 += ex2(fminf(ta, CL)); a1 += ex2(fminf(tb, CL));
                    }
                }
            } else {
                for (int c = w; c < 128; c += NW) {
                    const ulonglong2* x1 = (const ulonglong2*)(X1 + c * 16);
                    const ulonglong2* x2 = (const ulonglong2*)(X2 + c * 16);
                    const ulonglong2* qq = (const ulonglong2*)(Qx + c * 16);
                    #pragma unroll
                    for (int j = 0; j < 4; j++) {
                        ulonglong2 lx1 = x1[j], lx2 = x2[j], q = qq[j];
                        ull t; float ta, tb;
                        t = add2(fma2(Y1p, lx1.x, fma2(Y2p, lx2.x, q.x)), nR);
                        upk(t, ta, tb);
                        a0 += ex2(ta); a1 += ex2(tb);
                        t = add2(fma2(Y1p, lx1.y, fma2(Y2p, lx2.y, q.y)), nR);
                        upk(t, ta, tb);
                        a0 += ex2(ta); a1 += ex2(tb);
                    }
                }
            }
            sA[w * 64 + lane] = a0 + a1;
        }
        __syncthreads();
        if (tid < 32) {
            float A = 0.f;
            #pragma unroll
            for (int i = 0; i < NW; i++) A += sA[i * 64 + tid];
            A = fmaxf(A, 1e-30f);
            float Lse = sRg[tid] + lg2(A);
            sRg[tid] = Lse;
            if (tid < myn) g_gs[b * Pn + myc0 + tid] = l2bC[myc0 + tid] - Lse;  // Qy-form
        }
        bat_bar(b, ls);
        for (int i = tid; i < Pv; i += NT) Qyc[i] = __ldcg(&g_gs[b * Pn + i]);
        __syncthreads();
    }

    // ================= final transport distance =================
    {
        float q0 = Qx[fr0], q1 = Qx[fr1];
        float xna = 0.25f * (X1a * X1a + X2a * X2a);
        float xnb = 0.25f * (X1b_ * X1b_ + X2b_ * X2b_);
        float acc = 0.f;
        for (int c = w; c < nch; c += NW) {
            const ull* y1 = (const ull*)(Y1c + c * 16);
            const ull* y2 = (const ull*)(Y2c + c * 16);
            const ull* qq = (const ull*)(Qyc + c * 16);
            #pragma unroll
            for (int j = 0; j < 8; j++) {
                ull ly1 = y1[j], ly2 = y2[j], q = qq[j];
                ull t0 = fma2(X1A, ly1, fma2(X2A, ly2, q));
                ull t1 = fma2(X1B, ly1, fma2(X2B, ly2, q));
                float qa, qb, y1a, y1b, y2a, y2b, t0a, t0b, t1a, t1b;
                upk(q, qa, qb); upk(ly1, y1a, y1b); upk(ly2, y2a, y2b);
                upk(t0, t0a, t0b); upk(t1, t1a, t1b);
                float yna2 = y1a * y1a + y2a * y2a, ynb2 = y1b * y1b + y2b * y2b;
                acc = fmaf(ex2(fminf(t0a + q0, CL)), qa + yna2 + xna - t0a, acc);
                acc = fmaf(ex2(fminf(t0b + q0, CL)), qb + ynb2 + xna - t0b, acc);
                acc = fmaf(ex2(fminf(t1a + q1, CL)), qa + yna2 + xnb - t1a, acc);
                acc = fmaf(ex2(fminf(t1b + q1, CL)), qb + ynb2 + xnb - t1b, acc);
            }
        }
        acc = warp_sum(acc);
        if (lane == 0) sred[w] = acc;
    }
    __syncthreads();
    if (tid == 0) {
        float s = 0.f;
        #pragma unroll
        for (int i = 0; i < NW; i++) s += sred[i];
        g_part[blockIdx.x] = s;
    }

    // ---- grid-wide deterministic reduce ----
    __threadfence();
    __syncthreads();
    if (blockIdx.x == 0) {
        if (tid == 0) {
            atomicAdd(&g_gcnt, 1u);
            while (*((volatile unsigned*)&g_gcnt) < (unsigned)GRID) { }
            __threadfence();
        }
        __syncthreads();
        if (tid < 256) sA[tid] = __ldcg(&g_part[tid]);
        __syncthreads();
        #pragma unroll
        for (int o = 128; o; o >>= 1) {
            if (tid < o) sA[tid] += sA[tid + o];
            __syncthreads();
        }
        if (tid == 0) {
            out[0] = sA[0] * (1.f / (IL2 * (float)Bn));
            g_gcnt = 0;
        }
    } else {
        if (tid == 0) atomicAdd(&g_gcnt, 1u);
    }
}

extern "C" void kernel_launch(void* const* d_in, const int* in_sizes, int n_in,
                              void* d_out, int out_size) {
    const float* pred   = (const float*)d_in[0];
    const int*   labels = (const int*)d_in[1];
    const float* pos    = (const float*)d_in[2];
    float*       out    = (float*)d_out;

    sinkhorn_kernel<<<GRID, NT>>>(pred, labels, pos, out);
}